// round 6
// baseline (speedup 1.0000x reference)
#include <cuda_runtime.h>
#include <cstdint>

#define BATCH   8
#define CIN     256
#define HWPX    4096
#define WIDTH   64
#define CR      64
#define GROUPS  32
#define GCH     8

// intermediate y = relu6(bn(conv1(x)))  : [B][64][4096] = 8.4 MB (L2-resident)
__device__ __align__(16) float g_y[(size_t)BATCH * CR * HWPX];

typedef unsigned long long u64;

// ---------------- packed f32x2 helpers ----------------
__device__ __forceinline__ u64 ffma2(u64 a, u64 b, u64 c) {
    u64 d;
    asm("fma.rn.f32x2 %0, %1, %2, %3;" : "=l"(d) : "l"(a), "l"(b), "l"(c));
    return d;
}
__device__ __forceinline__ u64 pack2(float lo, float hi) {
    u64 d;
    asm("mov.b64 %0, {%1, %2};" : "=l"(d) : "f"(lo), "f"(hi));
    return d;
}
__device__ __forceinline__ float2 unpack2(u64 v) {
    float2 r;
    asm("mov.b64 {%0, %1}, %2;" : "=f"(r.x), "=f"(r.y) : "l"(v));
    return r;
}

// ---------------------------------------------------------------------------
// K1: conv1 (256->64) + BN + ReLU6 -> g_y
// grid (64 px-tiles of 64, 8 batch), 256 threads, 3 CTAs/SM
// smem: w1t [256ci][64co] f32 transposed (64KB)
// thread: 4 px (quad) x 4 co, x via LDG with prefetch depth 4 (MLP=4)
// ---------------------------------------------------------------------------
__global__ void __launch_bounds__(256, 3)
k1_conv1(const float* __restrict__ x,
         const float* __restrict__ w1, const float* __restrict__ b1,
         const float* __restrict__ gma, const float* __restrict__ bta,
         const float* __restrict__ mu,  const float* __restrict__ var)
{
    extern __shared__ float w1t[];                       // [256][64]
    const ulonglong2* w1tv = reinterpret_cast<const ulonglong2*>(w1t); // [256][16]

    const int tid = threadIdx.x;
    const int q   = tid & 15;          // px quad within 64-px tile
    const int cg  = tid >> 4;          // co group: 4 co = 1 ulonglong2
    const int b   = blockIdx.y;
    const int px0 = blockIdx.x * 64;

    // stage w1 transposed: w1t[ci][co] = w1[co][ci]
    #pragma unroll 8
    for (int k = 0; k < 64; ++k) {
        int i  = tid + k * 256;
        int co = i & 63, ci = i >> 6;
        w1t[ci * 64 + co] = w1[co * 256 + ci];
    }
    __syncthreads();

    u64 acc[2][4];
    #pragma unroll
    for (int c = 0; c < 2; ++c)
        #pragma unroll
        for (int j = 0; j < 4; ++j) acc[c][j] = 0ull;

    const float4* x4 = reinterpret_cast<const float4*>(x + (size_t)b * CIN * HWPX + px0) + q;

    // depth-4 prefetch pipeline over the 256 input channels
    float4 xbuf[4];
    #pragma unroll
    for (int i = 0; i < 4; ++i) xbuf[i] = x4[i * (HWPX / 4)];

    #pragma unroll 4
    for (int ci = 0; ci < 256; ++ci) {
        float4 xv = xbuf[ci & 3];
        if (ci < 252) xbuf[ci & 3] = x4[(ci + 4) * (HWPX / 4)];
        ulonglong2 wv = w1tv[ci * 16 + cg];   // {co0,co1},{co2,co3}
        u64 xx0 = pack2(xv.x, xv.x);
        u64 xx1 = pack2(xv.y, xv.y);
        u64 xx2 = pack2(xv.z, xv.z);
        u64 xx3 = pack2(xv.w, xv.w);
        acc[0][0] = ffma2(wv.x, xx0, acc[0][0]);
        acc[1][0] = ffma2(wv.y, xx0, acc[1][0]);
        acc[0][1] = ffma2(wv.x, xx1, acc[0][1]);
        acc[1][1] = ffma2(wv.y, xx1, acc[1][1]);
        acc[0][2] = ffma2(wv.x, xx2, acc[0][2]);
        acc[1][2] = ffma2(wv.y, xx2, acc[1][2]);
        acc[0][3] = ffma2(wv.x, xx3, acc[0][3]);
        acc[1][3] = ffma2(wv.y, xx3, acc[1][3]);
    }

    // BN + ReLU6 + store
    float4* y4 = reinterpret_cast<float4*>(g_y + (size_t)b * CR * HWPX + px0) + q;
    #pragma unroll
    for (int cp = 0; cp < 2; ++cp) {
        int co0 = cg * 4 + 2 * cp, co1 = co0 + 1;
        float s0  = __ldg(&gma[co0]) * rsqrtf(__ldg(&var[co0]) + 1e-5f);
        float bb0 = fmaf(__ldg(&b1[co0]), s0, __ldg(&bta[co0]) - __ldg(&mu[co0]) * s0);
        float s1  = __ldg(&gma[co1]) * rsqrtf(__ldg(&var[co1]) + 1e-5f);
        float bb1 = fmaf(__ldg(&b1[co1]), s1, __ldg(&bta[co1]) - __ldg(&mu[co1]) * s1);
        float4 r0, r1;
        float* r0f = reinterpret_cast<float*>(&r0);
        float* r1f = reinterpret_cast<float*>(&r1);
        #pragma unroll
        for (int j = 0; j < 4; ++j) {
            float2 f = unpack2(acc[cp][j]);
            r0f[j] = fminf(fmaxf(fmaf(f.x, s0, bb0), 0.f), 6.f);
            r1f[j] = fminf(fmaxf(fmaf(f.y, s1, bb1), 0.f), 6.f);
        }
        y4[(size_t)co0 * (HWPX / 4)] = r0;
        y4[(size_t)co1 * (HWPX / 4)] = r1;
    }
}

// ---------------------------------------------------------------------------
// K2: fused conv2 + involution, 5 tap-row passes
// grid (4 h-tiles of 16 rows, 32 groups, 8 batch) = 1024 CTAs, 256 th, 3 CTAs/SM
// smem: xh [8ch][20r][72c] = 46080B | w2d [64cr][5ti][6 u64 dup] = 15360B
// y via LDG from L2 with prefetch depth 2; ka initialized with bias (no add2)
// ---------------------------------------------------------------------------
__global__ void __launch_bounds__(256, 3)
k2_fused(const float* __restrict__ x,
         const float* __restrict__ w2, const float* __restrict__ b2,
         float* __restrict__ out)
{
    extern __shared__ char smraw[];
    float* xh = reinterpret_cast<float*>(smraw);                     // 46080 B
    const float4* xh4 = reinterpret_cast<const float4*>(smraw);
    u64* w2d = reinterpret_cast<u64*>(smraw + 46080);                // [64][5][6]

    const int tid = threadIdx.x;
    const int b   = blockIdx.z;
    const int g   = blockIdx.y;
    const int h0  = blockIdx.x * 16;
    const int px0 = h0 * WIDTH;
    const int q   = tid;          // quad: px = px0 + 4q
    const int r   = q >> 4;       // tile row 0..15
    const int c4  = q & 15;       // col quad

    // ---- stage x halo: 8 ch x 20 rows x 68 cols, pitch 72 ----
    const float* xb = x + ((size_t)b * CIN + g * GCH) * HWPX;
    for (int i = tid; i < 8 * 20 * 68; i += 256) {
        int c   = i / 1360;
        int rem = i - c * 1360;
        int rr  = rem / 68;
        int col = rem - rr * 68;
        int hy = h0 - 2 + rr, wx = col - 2;
        float v = 0.f;
        if ((unsigned)hy < 64u && (unsigned)wx < 64u)
            v = xb[c * HWPX + hy * WIDTH + wx];
        xh[c * 1440 + rr * 72 + col] = v;
    }
    // ---- stage w2 dup pairs: w2d[cr][ti][j] = {w,w}, j=5 pad ----
    for (int i = tid; i < 64 * 30; i += 256) {
        int cr  = i / 30;
        int rem = i - cr * 30;
        int ti  = rem / 6;
        int j   = rem - ti * 6;
        float v = (j < 5) ? w2[(size_t)(g * 25 + ti * 5 + j) * 64 + cr] : 0.f;
        w2d[cr * 30 + ti * 6 + j] = pack2(v, v);
    }
    __syncthreads();

    u64 o0[8], o1[8];
    #pragma unroll
    for (int c = 0; c < 8; ++c) { o0[c] = 0ull; o1[c] = 0ull; }

    // ulonglong2 = 4 floats -> one y channel = HWPX/4 = 1024 vector elements
    const ulonglong2* yp =
        reinterpret_cast<const ulonglong2*>(g_y + (size_t)b * CR * HWPX + px0) + q;

    #pragma unroll
    for (int ti = 0; ti < 5; ++ti) {
        // ---- conv2 partial: 5 taps of row ti; ka seeded with bias ----
        u64 ka0[5], ka1[5];
        #pragma unroll
        for (int j = 0; j < 5; ++j) {
            float bv = __ldg(b2 + g * 25 + ti * 5 + j);
            u64 bb = pack2(bv, bv);
            ka0[j] = bb; ka1[j] = bb;
        }

        // depth-2 prefetch pipeline over the 64 reduced channels
        ulonglong2 ybuf[2];
        ybuf[0] = yp[0];
        ybuf[1] = yp[HWPX / 4];

        #pragma unroll 4
        for (int cr = 0; cr < 64; ++cr) {
            ulonglong2 yv = ybuf[cr & 1];
            if (cr < 62) ybuf[cr & 1] = yp[(cr + 2) * (HWPX / 4)];
            const u64* wr = w2d + cr * 30 + ti * 6;
            ulonglong2 w01 = *reinterpret_cast<const ulonglong2*>(wr);
            ulonglong2 w23 = *reinterpret_cast<const ulonglong2*>(wr + 2);
            u64 w4 = wr[4];
            ka0[0] = ffma2(w01.x, yv.x, ka0[0]);
            ka1[0] = ffma2(w01.x, yv.y, ka1[0]);
            ka0[1] = ffma2(w01.y, yv.x, ka0[1]);
            ka1[1] = ffma2(w01.y, yv.y, ka1[1]);
            ka0[2] = ffma2(w23.x, yv.x, ka0[2]);
            ka1[2] = ffma2(w23.x, yv.y, ka1[2]);
            ka0[3] = ffma2(w23.y, yv.x, ka0[3]);
            ka1[3] = ffma2(w23.y, yv.y, ka1[3]);
            ka0[4] = ffma2(w4,    yv.x, ka0[4]);
            ka1[4] = ffma2(w4,    yv.y, ka1[4]);
        }

        // ---- involution contribution of kernel row ti ----
        #pragma unroll
        for (int c = 0; c < 8; ++c) {
            float4 wa = xh4[c * 360 + (r + ti) * 18 + c4];
            float4 wb = xh4[c * 360 + (r + ti) * 18 + c4 + 1];
            u64 p01 = pack2(wa.x, wa.y);
            u64 p12 = pack2(wa.y, wa.z);
            u64 p23 = pack2(wa.z, wa.w);
            u64 p34 = pack2(wa.w, wb.x);
            u64 p45 = pack2(wb.x, wb.y);
            u64 p56 = pack2(wb.y, wb.z);
            u64 p67 = pack2(wb.z, wb.w);
            u64 a = o0[c], bq = o1[c];
            a  = ffma2(ka0[0], p01, a);
            bq = ffma2(ka1[0], p23, bq);
            a  = ffma2(ka0[1], p12, a);
            bq = ffma2(ka1[1], p34, bq);
            a  = ffma2(ka0[2], p23, a);
            bq = ffma2(ka1[2], p45, bq);
            a  = ffma2(ka0[3], p34, a);
            bq = ffma2(ka1[3], p56, bq);
            a  = ffma2(ka0[4], p45, a);
            bq = ffma2(ka1[4], p67, bq);
            o0[c] = a; o1[c] = bq;
        }
    }

    // ---- store ----
    float* ob = out + ((size_t)b * CIN + g * GCH) * HWPX + px0 + 4 * q;
    #pragma unroll
    for (int c = 0; c < 8; ++c) {
        float2 f0 = unpack2(o0[c]);
        float2 f1 = unpack2(o1[c]);
        float4 rv; rv.x = f0.x; rv.y = f0.y; rv.z = f1.x; rv.w = f1.y;
        *reinterpret_cast<float4*>(ob + (size_t)c * HWPX) = rv;
    }
}

// ---------------------------------------------------------------------------
extern "C" void kernel_launch(void* const* d_in, const int* in_sizes, int n_in,
                              void* d_out, int out_size)
{
    const float* x   = (const float*)d_in[0];
    const float* w1  = (const float*)d_in[1];
    const float* b1  = (const float*)d_in[2];
    const float* gma = (const float*)d_in[3];
    const float* bta = (const float*)d_in[4];
    const float* mu  = (const float*)d_in[5];
    const float* var = (const float*)d_in[6];
    const float* w2  = (const float*)d_in[7];
    const float* b2  = (const float*)d_in[8];
    float* out = (float*)d_out;

    const int SMEM1 = 65536;            // w1t
    const int SMEM2 = 46080 + 15360;    // 61440 B
    cudaFuncSetAttribute(k1_conv1, cudaFuncAttributeMaxDynamicSharedMemorySize, SMEM1);
    cudaFuncSetAttribute(k2_fused, cudaFuncAttributeMaxDynamicSharedMemorySize, SMEM2);

    k1_conv1<<<dim3(64, 8), 256, SMEM1>>>(x, w1, b1, gma, bta, mu, var);
    k2_fused<<<dim3(4, 32, 8), 256, SMEM2>>>(x, w2, b2, out);
}

// round 7
// speedup vs baseline: 1.3607x; 1.3607x over previous
#include <cuda_runtime.h>
#include <cstdint>

#define BATCH   8
#define CIN     256
#define HWPX    4096
#define WIDTH   64
#define CR      64
#define GROUPS  32
#define GCH     8

// intermediate y = relu6(bn(conv1(x)))  : [B][64][4096] = 8.4 MB (L2-resident)
__device__ __align__(16) float g_y[(size_t)BATCH * CR * HWPX];

typedef unsigned long long u64;

// ---------------- packed f32x2 helpers ----------------
__device__ __forceinline__ u64 ffma2(u64 a, u64 b, u64 c) {
    u64 d;
    asm("fma.rn.f32x2 %0, %1, %2, %3;" : "=l"(d) : "l"(a), "l"(b), "l"(c));
    return d;
}
__device__ __forceinline__ u64 pack2(float lo, float hi) {
    u64 d;
    asm("mov.b64 %0, {%1, %2};" : "=l"(d) : "f"(lo), "f"(hi));
    return d;
}
__device__ __forceinline__ float2 unpack2(u64 v) {
    float2 r;
    asm("mov.b64 {%0, %1}, %2;" : "=f"(r.x), "=f"(r.y) : "l"(v));
    return r;
}

// ---------------------------------------------------------------------------
// K1: conv1 (256->64) + BN + ReLU6 -> g_y
// grid (32 px-tiles of 128, 8 batch) = 256 CTAs, 256 threads, 2 CTAs/SM
// smem: w1t [256ci][64co] transposed (64KB)
// warp = 32 lanes x float4 = fully-coalesced 512B LDG per channel
// thread: 1 quad x 8 co (acc 4x4 u64), lookahead-1 on x
// ---------------------------------------------------------------------------
__global__ void __launch_bounds__(256, 2)
k1_conv1(const float* __restrict__ x,
         const float* __restrict__ w1, const float* __restrict__ b1,
         const float* __restrict__ gma, const float* __restrict__ bta,
         const float* __restrict__ mu,  const float* __restrict__ var)
{
    extern __shared__ float w1t[];                                     // [256][64]
    const ulonglong2* w1tv = reinterpret_cast<const ulonglong2*>(w1t); // [256][16]

    const int tid  = threadIdx.x;
    const int lane = tid & 31;         // px quad (32 quads = 128 px)
    const int cg   = tid >> 5;         // co group: 8 co
    const int b    = blockIdx.y;
    const int px0  = blockIdx.x * 128;

    // stage w1 transposed: w1t[ci][co] = w1[co][ci]
    #pragma unroll 8
    for (int k = 0; k < 64; ++k) {
        int i  = tid + k * 256;
        int co = i & 63, ci = i >> 6;
        w1t[ci * 64 + co] = w1[co * 256 + ci];
    }
    __syncthreads();

    u64 acc[4][4];
    #pragma unroll
    for (int k = 0; k < 4; ++k)
        #pragma unroll
        for (int j = 0; j < 4; ++j) acc[k][j] = 0ull;

    const float4* x4 = reinterpret_cast<const float4*>(x + (size_t)b * CIN * HWPX + px0) + lane;

    float4 xv = x4[0];
    #pragma unroll 4
    for (int ci = 0; ci < 256; ++ci) {
        float4 xn = (ci < 255) ? x4[(ci + 1) * (HWPX / 4)] : xv;
        ulonglong2 wv0 = w1tv[ci * 16 + cg * 2];       // co pairs {0,1},{2,3}
        ulonglong2 wv1 = w1tv[ci * 16 + cg * 2 + 1];   // co pairs {4,5},{6,7}
        u64 xx0 = pack2(xv.x, xv.x);
        u64 xx1 = pack2(xv.y, xv.y);
        u64 xx2 = pack2(xv.z, xv.z);
        u64 xx3 = pack2(xv.w, xv.w);
        acc[0][0] = ffma2(wv0.x, xx0, acc[0][0]);
        acc[0][1] = ffma2(wv0.x, xx1, acc[0][1]);
        acc[0][2] = ffma2(wv0.x, xx2, acc[0][2]);
        acc[0][3] = ffma2(wv0.x, xx3, acc[0][3]);
        acc[1][0] = ffma2(wv0.y, xx0, acc[1][0]);
        acc[1][1] = ffma2(wv0.y, xx1, acc[1][1]);
        acc[1][2] = ffma2(wv0.y, xx2, acc[1][2]);
        acc[1][3] = ffma2(wv0.y, xx3, acc[1][3]);
        acc[2][0] = ffma2(wv1.x, xx0, acc[2][0]);
        acc[2][1] = ffma2(wv1.x, xx1, acc[2][1]);
        acc[2][2] = ffma2(wv1.x, xx2, acc[2][2]);
        acc[2][3] = ffma2(wv1.x, xx3, acc[2][3]);
        acc[3][0] = ffma2(wv1.y, xx0, acc[3][0]);
        acc[3][1] = ffma2(wv1.y, xx1, acc[3][1]);
        acc[3][2] = ffma2(wv1.y, xx2, acc[3][2]);
        acc[3][3] = ffma2(wv1.y, xx3, acc[3][3]);
        xv = xn;
    }

    // BN + ReLU6 + store
    float4* y4 = reinterpret_cast<float4*>(g_y + (size_t)b * CR * HWPX + px0) + lane;
    #pragma unroll
    for (int k = 0; k < 4; ++k) {
        int co0 = cg * 8 + 2 * k, co1 = co0 + 1;
        float s0  = __ldg(&gma[co0]) * rsqrtf(__ldg(&var[co0]) + 1e-5f);
        float bb0 = fmaf(__ldg(&b1[co0]), s0, __ldg(&bta[co0]) - __ldg(&mu[co0]) * s0);
        float s1  = __ldg(&gma[co1]) * rsqrtf(__ldg(&var[co1]) + 1e-5f);
        float bb1 = fmaf(__ldg(&b1[co1]), s1, __ldg(&bta[co1]) - __ldg(&mu[co1]) * s1);
        float4 r0, r1;
        float* r0f = reinterpret_cast<float*>(&r0);
        float* r1f = reinterpret_cast<float*>(&r1);
        #pragma unroll
        for (int j = 0; j < 4; ++j) {
            float2 f = unpack2(acc[k][j]);
            r0f[j] = fminf(fmaxf(fmaf(f.x, s0, bb0), 0.f), 6.f);
            r1f[j] = fminf(fmaxf(fmaf(f.y, s1, bb1), 0.f), 6.f);
        }
        y4[(size_t)co0 * (HWPX / 4)] = r0;
        y4[(size_t)co1 * (HWPX / 4)] = r1;
    }
}

// ---------------------------------------------------------------------------
// K2: fused conv2 + involution, SINGLE pass over all 25 taps.
// grid (8 h-tiles of 8 rows, 32 groups, 8 batch) = 2048 CTAs, 256 th, 2 CTAs/SM
// Thread owns a pixel PAIR (px = 2*tid): ka = [5 rows][3 tap-pairs] u64 per px.
// smem: xh [8ch][12r][72c] f32 = 27648B | w2p [64cr][32f] (5 rows x 6, pad) = 8192B
// y read ONCE per cr via LDG.64 (depth-4 rolling); w2 row = 8 LDS.128, pairs
// come out of ulonglong2 halves -> zero repacking ALU in the hot loop.
// ---------------------------------------------------------------------------
__global__ void __launch_bounds__(256, 2)
k2_fused(const float* __restrict__ x,
         const float* __restrict__ w2, const float* __restrict__ b2,
         float* __restrict__ out)
{
    extern __shared__ char smraw[];
    float* xh  = reinterpret_cast<float*>(smraw);                 // 27648 B
    float* w2p = reinterpret_cast<float*>(smraw + 27648);         // 8192 B

    const int tid = threadIdx.x;
    const int b   = blockIdx.z;
    const int g   = blockIdx.y;
    const int h0  = blockIdx.x * 8;
    const int px0 = h0 * WIDTH;
    const int rr  = tid >> 5;        // tile row 0..7
    const int col = (tid & 31) * 2;  // column of px0 of the pair

    // ---- stage x halo: 8 ch x 12 rows x 68 cols, pitch 72 ----
    const float* xb = x + ((size_t)b * CIN + g * GCH) * HWPX;
    for (int i = tid; i < 8 * 12 * 68; i += 256) {
        int c   = i / 816;
        int rem = i - c * 816;
        int r2  = rem / 68;
        int cc  = rem - r2 * 68;
        int hy = h0 - 2 + r2, wx = cc - 2;
        float v = 0.f;
        if ((unsigned)hy < 64u && (unsigned)wx < 64u)
            v = xb[c * HWPX + hy * WIDTH + wx];
        xh[c * 864 + r2 * 72 + cc] = v;
    }
    // ---- stage w2p[cr][ti*6+j] = w2[(g*25+5ti+j)*64+cr], j=5 & tail = 0 ----
    for (int i = tid; i < 64 * 32; i += 256) {
        int cr  = i >> 5;
        int rem = i & 31;
        int ti  = rem / 6;
        int j   = rem - ti * 6;
        float v = (ti < 5 && j < 5) ? w2[(size_t)(g * 25 + ti * 5 + j) * 64 + cr] : 0.f;
        w2p[cr * 32 + rem] = v;
    }
    __syncthreads();

    // ---- ka seeded with bias: pairs {tap 5ti+2k, 5ti+2k+1}, k=2 -> {tap+4, 0}
    u64 kaA[5][3], kaB[5][3];
    #pragma unroll
    for (int ti = 0; ti < 5; ++ti) {
        float t0 = __ldg(b2 + g * 25 + ti * 5 + 0);
        float t1 = __ldg(b2 + g * 25 + ti * 5 + 1);
        float t2 = __ldg(b2 + g * 25 + ti * 5 + 2);
        float t3 = __ldg(b2 + g * 25 + ti * 5 + 3);
        float t4 = __ldg(b2 + g * 25 + ti * 5 + 4);
        kaA[ti][0] = pack2(t0, t1); kaB[ti][0] = kaA[ti][0];
        kaA[ti][1] = pack2(t2, t3); kaB[ti][1] = kaA[ti][1];
        kaA[ti][2] = pack2(t4, 0.f); kaB[ti][2] = kaA[ti][2];
    }

    // ---- conv2: single pass over 64 reduced channels ----
    const u64* yp = reinterpret_cast<const u64*>(g_y + (size_t)b * CR * HWPX + px0) + tid;
    u64 ybuf[4];
    #pragma unroll
    for (int i = 0; i < 4; ++i) ybuf[i] = yp[(size_t)i * (HWPX / 2)];

    #pragma unroll 4
    for (int cr = 0; cr < 64; ++cr) {
        u64 yv = ybuf[cr & 3];
        if (cr < 60) ybuf[cr & 3] = yp[(size_t)(cr + 4) * (HWPX / 2)];
        float2 yf = unpack2(yv);
        u64 y00 = pack2(yf.x, yf.x);
        u64 y11 = pack2(yf.y, yf.y);

        const ulonglong2* wr = reinterpret_cast<const ulonglong2*>(w2p + cr * 32);
        ulonglong2 wv[8];
        #pragma unroll
        for (int m = 0; m < 8; ++m) wv[m] = wr[m];

        #pragma unroll
        for (int ti = 0; ti < 5; ++ti) {
            #pragma unroll
            for (int k = 0; k < 3; ++k) {
                int m = ti * 3 + k;                              // u64 index 0..14
                u64 w = (m & 1) ? wv[m >> 1].y : wv[m >> 1].x;   // {w[2m], w[2m+1]}
                kaA[ti][k] = ffma2(w, y00, kaA[ti][k]);
                kaB[ti][k] = ffma2(w, y11, kaB[ti][k]);
            }
        }
    }

    // ---- involution + store (per channel, fold pair lanes at the end) ----
    #pragma unroll
    for (int c = 0; c < 8; ++c) {
        u64 oA = 0ull, oB = 0ull;
        #pragma unroll
        for (int ti = 0; ti < 5; ++ti) {
            const float2* xr =
                reinterpret_cast<const float2*>(xh + c * 864 + (rr + ti) * 72 + col);
            float2 f0 = xr[0], f1 = xr[1], f2 = xr[2];    // w[0..5]
            u64 q0 = pack2(f0.x, f0.y);   // px0: {w0,w1}
            u64 q1 = pack2(f1.x, f1.y);   //      {w2,w3}
            u64 q2 = pack2(f2.x, f2.y);   //      {w4, ignored (ka pad=0)}
            u64 s0 = pack2(f0.y, f1.x);   // px1: {w1,w2}
            u64 s1 = pack2(f1.y, f2.x);   //      {w3,w4}
            u64 s2 = pack2(f2.y, f2.y);   //      {w5, ignored}
            oA = ffma2(kaA[ti][0], q0, oA);
            oA = ffma2(kaA[ti][1], q1, oA);
            oA = ffma2(kaA[ti][2], q2, oA);
            oB = ffma2(kaB[ti][0], s0, oB);
            oB = ffma2(kaB[ti][1], s1, oB);
            oB = ffma2(kaB[ti][2], s2, oB);
        }
        float2 a = unpack2(oA);
        float2 bb = unpack2(oB);
        float2 rv;
        rv.x = a.x + a.y;    // px0 = even taps + odd taps
        rv.y = bb.x + bb.y;  // px1
        *reinterpret_cast<float2*>(
            out + ((size_t)b * CIN + g * GCH + c) * HWPX + px0 + rr * WIDTH + col) = rv;
    }
}

// ---------------------------------------------------------------------------
extern "C" void kernel_launch(void* const* d_in, const int* in_sizes, int n_in,
                              void* d_out, int out_size)
{
    const float* x   = (const float*)d_in[0];
    const float* w1  = (const float*)d_in[1];
    const float* b1  = (const float*)d_in[2];
    const float* gma = (const float*)d_in[3];
    const float* bta = (const float*)d_in[4];
    const float* mu  = (const float*)d_in[5];
    const float* var = (const float*)d_in[6];
    const float* w2  = (const float*)d_in[7];
    const float* b2  = (const float*)d_in[8];
    float* out = (float*)d_out;

    const int SMEM1 = 65536;          // w1t
    const int SMEM2 = 27648 + 8192;   // 35840 B
    cudaFuncSetAttribute(k1_conv1, cudaFuncAttributeMaxDynamicSharedMemorySize, SMEM1);
    cudaFuncSetAttribute(k2_fused, cudaFuncAttributeMaxDynamicSharedMemorySize, SMEM2);

    k1_conv1<<<dim3(32, 8), 256, SMEM1>>>(x, w1, b1, gma, bta, mu, var);
    k2_fused<<<dim3(8, 32, 8), 256, SMEM2>>>(x, w2, b2, out);
}